// round 14
// baseline (speedup 1.0000x reference)
#include <cuda_runtime.h>
#include <cuda_fp16.h>
#include <math.h>
#include <stdint.h>

// ---------------- problem constants ----------------
#define S     2048
#define HID   2560
#define NH    8
#define NKV   4
#define DH    256
#define WIN   1024
#define QN    (NH*DH)    // 2048
#define KVN   (NKV*DH)   // 1024

// ---------------- scratch ----------------
__device__ float g_q[S * QN];
__device__ float g_k[S * KVN];
__device__ float g_v[S * KVN];

__device__ __half g_hs_h[S * HID],  g_hs_l[S * HID];
__device__ __half g_wq_h[HID * QN], g_wq_l[HID * QN];
__device__ __half g_wk_h[HID * KVN], g_wk_l[HID * KVN];
__device__ __half g_wv_h[HID * KVN];
__device__ __half g_wo_h[QN * HID];
__device__ __half g_at_h[S * QN];

__device__ __half g_qh[S * QN],  g_ql[S * QN];
__device__ __half g_kh[S * KVN], g_kl[S * KVN];
__device__ __half g_vh[S * KVN];

// ---------------- PTX helpers ----------------
#define CP16(dst_u32, src_ptr) \
    asm volatile("cp.async.cg.shared.global [%0], [%1], 16;\n" :: "r"(dst_u32), "l"(src_ptr))
#define CP_COMMIT()  asm volatile("cp.async.commit_group;\n")
#define CP_WAIT0()   asm volatile("cp.async.wait_group 0;\n" ::: "memory")

#define LDSM4(R, addr) \
    asm volatile("ldmatrix.sync.aligned.m8n8.x4.shared.b16 {%0,%1,%2,%3}, [%4];\n" \
        : "=r"((R)[0]), "=r"((R)[1]), "=r"((R)[2]), "=r"((R)[3]) : "r"(addr))
#define LDSM4T(R, addr) \
    asm volatile("ldmatrix.sync.aligned.m8n8.x4.trans.shared.b16 {%0,%1,%2,%3}, [%4];\n" \
        : "=r"((R)[0]), "=r"((R)[1]), "=r"((R)[2]), "=r"((R)[3]) : "r"(addr))

#define MMA_FP16(d, a, b0, b1) \
    asm volatile("mma.sync.aligned.m16n8k16.row.col.f32.f16.f16.f32 " \
        "{%0,%1,%2,%3},{%4,%5,%6,%7},{%8,%9},{%0,%1,%2,%3};\n" \
        : "+f"((d)[0]), "+f"((d)[1]), "+f"((d)[2]), "+f"((d)[3]) \
        : "r"((a)[0]), "r"((a)[1]), "r"((a)[2]), "r"((a)[3]), "r"(b0), "r"(b1))

#define MMA_F16A(d, a, b0, b1) \
    asm volatile("mma.sync.aligned.m16n8k16.row.col.f16.f16.f16.f16 " \
        "{%0,%1},{%2,%3,%4,%5},{%6,%7},{%0,%1};\n" \
        : "+r"((d)[0]), "+r"((d)[1]) \
        : "r"((a)[0]), "r"((a)[1]), "r"((a)[2]), "r"((a)[3]), "r"(b0), "r"(b1))

__device__ __forceinline__ uint32_t smem_u32(const void* p) {
    return (uint32_t)__cvta_generic_to_shared(p);
}
__device__ __forceinline__ void add_h2(float* f01, uint32_t packed) {
    __half2 h = *(__half2*)&packed;
    float2 v = __half22float2(h);
    f01[0] += v.x; f01[1] += v.y;
}
// XOR swizzle for 512B rows
__device__ __forceinline__ uint32_t swz(int row, int cb) {
    return (uint32_t)(row * 512 + ((cb ^ (row & 7)) << 4));
}

// =====================================================================
// Fused split kernel (one launch). wq,wk: hi/lo. wv,wo: hi only.
// blocks: [0,5120) hs | [5120,10240) wq | [10240,12800) wk
//         [12800,15360) wv | [15360,20480) wo
// =====================================================================
__global__ __launch_bounds__(256) void split_all_kernel(
    const float* __restrict__ hs, const float* __restrict__ wq,
    const float* __restrict__ wk, const float* __restrict__ wv,
    const float* __restrict__ wo,
    __half* __restrict__ hsh, __half* __restrict__ hsl,
    __half* __restrict__ wqh, __half* __restrict__ wql,
    __half* __restrict__ wkh, __half* __restrict__ wkl,
    __half* __restrict__ wvh, __half* __restrict__ woh)
{
    int b = blockIdx.x;
    const float* x; __half *h, *l;
    if (b < 5120)       { x = hs; h = hsh; l = hsl; }
    else if (b < 10240) { x = wq; h = wqh; l = wql; b -= 5120; }
    else if (b < 12800) { x = wk; h = wkh; l = wkl; b -= 10240; }
    else if (b < 15360) { x = wv; h = wvh; l = nullptr; b -= 12800; }
    else                { x = wo; h = woh; l = nullptr; b -= 15360; }

    int i = (b * 256 + threadIdx.x) * 4;
    float4 v = *(const float4*)(x + i);
    __half h0 = __float2half_rn(v.x), h1 = __float2half_rn(v.y);
    __half h2 = __float2half_rn(v.z), h3 = __float2half_rn(v.w);
    *(__half2*)(h + i)     = __halves2half2(h0, h1);
    *(__half2*)(h + i + 2) = __halves2half2(h2, h3);
    if (l) {
        *(__half2*)(l + i)     = __halves2half2(
            __float2half_rn(v.x - __half2float(h0)), __float2half_rn(v.y - __half2float(h1)));
        *(__half2*)(l + i + 2) = __halves2half2(
            __float2half_rn(v.z - __half2float(h2)), __float2half_rn(v.w - __half2float(h3)));
    }
}

// =====================================================================
// fp16 TC GEMM body — PASSES compile-time. 64-row M tiles, K-chunk 64.
//  PASSES=1: C = Ah*Bh (f32acc)
//  PASSES=2: += Al*Bh (f16acc)
//  PASSES=3: += Ah*Bl (f16acc)
// A tile 64x64 (stride 72), B tile 64x128 (stride 136). 8 warps.
// =====================================================================
#define A64_STR 72
#define B64_STR 136
#define A64_E   (64 * A64_STR)
#define B64_E   (64 * B64_STR)
#define G64_BUF (2 * A64_E + 2 * B64_E)
#define GEMM64_SMEM (2 * G64_BUF * 2)      // 106496 B

template <int PASSES>
__device__ __forceinline__ void gemm_body(
    const __half* __restrict__ Ah, const __half* __restrict__ Al,
    const __half* __restrict__ Bh, const __half* __restrict__ Bl,
    float* __restrict__ C, int N, int K, int m0, int n0,
    __half* smbuf)
{
    const int t    = threadIdx.x;
    const int lane = t & 31;
    const int wid  = t >> 5;
    const int wm   = wid >> 2;           // 0..1 (32-row slab)
    const int wn   = wid & 3;

    float acc[2][4][4];
    uint32_t accL[2][4][2];
#pragma unroll
    for (int mi = 0; mi < 2; mi++)
#pragma unroll
        for (int ni = 0; ni < 4; ni++) {
#pragma unroll
            for (int r = 0; r < 4; r++) acc[mi][ni][r] = 0.f;
            accL[mi][ni][0] = 0u; accL[mi][ni][1] = 0u;
        }

    uint32_t sbase[2][4];
#pragma unroll
    for (int b = 0; b < 2; b++) {
        __half* p = smbuf + b * G64_BUF;
        sbase[b][0] = smem_u32(p);
        sbase[b][1] = smem_u32(p + A64_E);
        sbase[b][2] = smem_u32(p + 2 * A64_E);
        sbase[b][3] = smem_u32(p + 2 * A64_E + B64_E);
    }

    auto issue = [&](int k0, int buf) {
#pragma unroll
        for (int p = 0; p < 2; p++) {               // A: 64x64
            int id = t + p * 256;
            int row = id >> 3, c8 = (id & 7) * 8;
            size_t aoff = (size_t)(m0 + row) * K + k0 + c8;
            uint32_t ad = (uint32_t)(row * A64_STR + c8) * 2;
            CP16(sbase[buf][0] + ad, Ah + aoff);
            if (PASSES >= 2) CP16(sbase[buf][1] + ad, Al + aoff);
        }
#pragma unroll
        for (int p = 0; p < 4; p++) {               // B: 64x128
            int id = t + p * 256;
            int row = id >> 4, c8 = (id & 15) * 8;
            size_t boff = (size_t)(k0 + row) * N + n0 + c8;
            uint32_t bd = (uint32_t)(row * B64_STR + c8) * 2;
            CP16(sbase[buf][2] + bd, Bh + boff);
            if (PASSES == 3) CP16(sbase[buf][3] + bd, Bl + boff);
        }
        CP_COMMIT();
    };

    issue(0, 0);
    const int nIter = K / 64;

    for (int it = 0; it < nIter; it++) {
        CP_WAIT0();
        __syncthreads();
        if (it + 1 < nIter) issue((it + 1) * 64, (it + 1) & 1);

        const int buf = it & 1;
        const uint32_t ah_s = sbase[buf][0];
        const uint32_t al_s = sbase[buf][1];
        const uint32_t bh_s = sbase[buf][2];
        const uint32_t bl_s = sbase[buf][3];

#pragma unroll
        for (int ks = 0; ks < 64; ks += 16) {
            uint32_t fah[2][4], fal[2][4], fbh[2][4], fbl[2][4];

            int arow = lane & 15;
            int acol = ks + ((lane >> 4) & 1) * 8;
#pragma unroll
            for (int mi = 0; mi < 2; mi++) {
                uint32_t off = (uint32_t)((wm * 32 + mi * 16 + arow) * A64_STR + acol) * 2;
                LDSM4(fah[mi], ah_s + off);
                if (PASSES >= 2) LDSM4(fal[mi], al_s + off);
            }

            int bkrow = ks + (lane & 7) + ((lane >> 3) & 1) * 8;
#pragma unroll
            for (int np = 0; np < 2; np++) {
                int bcol = wn * 32 + np * 16 + ((lane >> 4) & 1) * 8;
                uint32_t off = (uint32_t)(bkrow * B64_STR + bcol) * 2;
                LDSM4T(fbh[np], bh_s + off);
                if (PASSES == 3) LDSM4T(fbl[np], bl_s + off);
            }

#pragma unroll
            for (int mi = 0; mi < 2; mi++)
#pragma unroll
                for (int ni = 0; ni < 4; ni++) {
                    const uint32_t* bh2 = &fbh[ni >> 1][(ni & 1) * 2];
                    MMA_FP16(acc[mi][ni], fah[mi], bh2[0], bh2[1]);
                    if (PASSES >= 2) MMA_F16A(accL[mi][ni], fal[mi], bh2[0], bh2[1]);
                    if (PASSES == 3) {
                        const uint32_t* bl2 = &fbl[ni >> 1][(ni & 1) * 2];
                        MMA_F16A(accL[mi][ni], fah[mi], bl2[0], bl2[1]);
                    }
                }
        }
        __syncthreads();
    }

    int g  = lane >> 2;
    int c2 = (lane & 3) * 2;
#pragma unroll
    for (int mi = 0; mi < 2; mi++)
#pragma unroll
        for (int ni = 0; ni < 4; ni++) {
            if (PASSES >= 2) {
                add_h2(&acc[mi][ni][0], accL[mi][ni][0]);
                add_h2(&acc[mi][ni][2], accL[mi][ni][1]);
            }
            int row = m0 + wm * 32 + mi * 16 + g;
            int col = n0 + wn * 32 + ni * 8 + c2;
            *(float2*)(C + (size_t)row * N + col)       = make_float2(acc[mi][ni][0], acc[mi][ni][1]);
            *(float2*)(C + (size_t)(row + 8) * N + col) = make_float2(acc[mi][ni][2], acc[mi][ni][3]);
        }
}

// fused QKV projection — q 3-pass; k 3-pass (REVERTED); v 1-pass
__global__ __launch_bounds__(256) void gemm_qkv_kernel(
    const __half* __restrict__ Ah, const __half* __restrict__ Al,
    const __half* __restrict__ wqh, const __half* __restrict__ wql,
    const __half* __restrict__ wkh, const __half* __restrict__ wkl,
    const __half* __restrict__ wvh,
    float* __restrict__ gq, float* __restrict__ gk, float* __restrict__ gv)
{
    extern __shared__ __half smbuf[];
    const int bx = blockIdx.x;
    const int m0 = blockIdx.y * 64;
    if (bx < 16)
        gemm_body<3>(Ah, Al, wqh, wql, gq, QN, HID, m0, bx * 128, smbuf);
    else if (bx < 24)
        gemm_body<3>(Ah, Al, wkh, wkl, gk, KVN, HID, m0, (bx - 16) * 128, smbuf);
    else
        gemm_body<1>(Ah, Ah, wvh, wvh, gv, KVN, HID, m0, (bx - 24) * 128, smbuf);
}

// output projection — 1-pass (linear path)
__global__ __launch_bounds__(256) void gemm_wo_kernel(
    const __half* __restrict__ Ah,
    const __half* __restrict__ Bh, float* __restrict__ C)
{
    extern __shared__ __half smbuf[];
    gemm_body<1>(Ah, Ah, Bh, Bh, C, HID, QN, blockIdx.y * 64, blockIdx.x * 128, smbuf);
}

// =====================================================================
// Fused RMSNorm (+weight) + RoPE — warp-per-head (unchanged)
// =====================================================================
__global__ __launch_bounds__(256) void norm_rope_kernel(
    const float* __restrict__ q, const float* __restrict__ k, const float* __restrict__ v,
    const float* __restrict__ cosp, const float* __restrict__ sinp,
    const float* __restrict__ qw, const float* __restrict__ kw,
    __half* __restrict__ qh, __half* __restrict__ ql,
    __half* __restrict__ kh, __half* __restrict__ kl,
    __half* __restrict__ vh)
{
    const int lane = threadIdx.x & 31;
    const int row  = blockIdx.x * 8 + (threadIdx.x >> 5);
    const int s    = row >> 4;
    const int idx  = row & 15;

    const float* base;
    const float* w;
    __half *oh, *ol;
    bool rope;
    if (idx < 8) {
        base = q + (size_t)s * QN + idx * DH; w = qw; rope = true;
        oh = qh + (size_t)s * QN + idx * DH; ol = ql + (size_t)s * QN + idx * DH;
    } else if (idx < 12) {
        base = k + (size_t)s * KVN + (idx - 8) * DH; w = kw; rope = true;
        oh = kh + (size_t)s * KVN + (idx - 8) * DH; ol = kl + (size_t)s * KVN + (idx - 8) * DH;
    } else {
        base = v + (size_t)s * KVN + (idx - 12) * DH; w = nullptr; rope = false;
        oh = vh + (size_t)s * KVN + (idx - 12) * DH; ol = nullptr;
    }

    const int d0 = lane * 8;
    float x[8];
    *(float4*)&x[0] = *(const float4*)(base + d0);
    *(float4*)&x[4] = *(const float4*)(base + d0 + 4);

    float ss = 0.f;
#pragma unroll
    for (int j = 0; j < 8; j++) ss += x[j] * x[j];
#pragma unroll
    for (int o = 16; o; o >>= 1) ss += __shfl_xor_sync(0xffffffffu, ss, o);

    float inv = rsqrtf(ss * (1.0f / 256.0f) + 1e-6f);
    float y[8];
#pragma unroll
    for (int j = 0; j < 8; j++) y[j] = x[j] * inv;
    if (w) {
        float wv[8];
        *(float4*)&wv[0] = *(const float4*)(w + d0);
        *(float4*)&wv[4] = *(const float4*)(w + d0 + 4);
#pragma unroll
        for (int j = 0; j < 8; j++) y[j] *= wv[j];
    }

    float out[8];
    if (rope) {
        float c[8], si[8];
        *(float4*)&c[0]  = *(const float4*)(cosp + (size_t)s * DH + d0);
        *(float4*)&c[4]  = *(const float4*)(cosp + (size_t)s * DH + d0 + 4);
        *(float4*)&si[0] = *(const float4*)(sinp + (size_t)s * DH + d0);
        *(float4*)&si[4] = *(const float4*)(sinp + (size_t)s * DH + d0 + 4);
#pragma unroll
        for (int j = 0; j < 8; j++) {
            float pv = __shfl_xor_sync(0xffffffffu, y[j], 16);
            float rh = (lane < 16) ? -pv : pv;
            out[j] = y[j] * c[j] + rh * si[j];
        }
    } else {
#pragma unroll
        for (int j = 0; j < 8; j++) out[j] = y[j];
    }

    __half hi8[8], lo8[8];
#pragma unroll
    for (int j = 0; j < 8; j++) {
        hi8[j] = __float2half_rn(out[j]);
        lo8[j] = __float2half_rn(out[j] - __half2float(hi8[j]));
    }
    *(uint4*)(oh + d0) = *(uint4*)hi8;
    if (ol) *(uint4*)(ol + d0) = *(uint4*)lo8;
}

// =====================================================================
// TC flash attention: 64-q tiles, 4 warps, 2 CTAs/SM.
// QK 3-pass; PV single-pass; split K/V prefetch hides load latency:
// K(kb+1) issued right after QK reads finish (overlaps softmax+PV);
// V(kb+1) issued after PV reads finish.
// =====================================================================
#define ATT_SM_BYTES (2 * 64 * 512 + 3 * 32 * 512)   // 114688

__global__ __launch_bounds__(128, 2) void attn_tc_kernel(
    const __half* __restrict__ Qh, const __half* __restrict__ Ql,
    const __half* __restrict__ Kh, const __half* __restrict__ Kl,
    const __half* __restrict__ Vh,
    __half* __restrict__ Oh)
{
    extern __shared__ __half sm2[];
    const int t    = threadIdx.x;
    const int lane = t & 31;
    const int w    = t >> 5;
    const int q0   = blockIdx.x * 64;
    const int h    = blockIdx.y;
    const int kvh  = h >> 1;

    const uint32_t sQh = smem_u32(sm2);
    const uint32_t sQl = sQh + 64 * 512;
    const uint32_t sKh = sQl + 64 * 512;
    const uint32_t sKl = sKh + 32 * 512;
    const uint32_t sVh = sKl + 32 * 512;

    // ---- Q load ----
    const __half* gqh = Qh + (size_t)q0 * QN + h * DH;
    const __half* gql = Ql + (size_t)q0 * QN + h * DH;
#pragma unroll
    for (int it = 0; it < 16; it++) {
        int id = t + it * 128;
        int row = id >> 5, cb = id & 31;
        uint32_t d = swz(row, cb);
        size_t g = (size_t)row * QN + cb * 8;
        CP16(sQh + d, gqh + g);
        CP16(sQl + d, gql + g);
    }
    CP_COMMIT();

    auto issueK = [&](int k0) {
        const __half* gkh = Kh + (size_t)k0 * KVN + kvh * DH;
        const __half* gkl = Kl + (size_t)k0 * KVN + kvh * DH;
#pragma unroll
        for (int it = 0; it < 8; it++) {
            int id = t + it * 128;
            int row = id >> 5, cb = id & 31;
            uint32_t d = swz(row, cb);
            size_t g = (size_t)row * KVN + cb * 8;
            CP16(sKh + d, gkh + g);
            CP16(sKl + d, gkl + g);
        }
        CP_COMMIT();
    };
    auto issueV = [&](int k0) {
        const __half* gvh = Vh + (size_t)k0 * KVN + kvh * DH;
#pragma unroll
        for (int it = 0; it < 8; it++) {
            int id = t + it * 128;
            int row = id >> 5, cb = id & 31;
            uint32_t d = swz(row, cb);
            CP16(sVh + d, gvh + (size_t)row * KVN + cb * 8);
        }
        CP_COMMIT();
    };

    float o[32][4];
#pragma unroll
    for (int dt = 0; dt < 32; dt++)
#pragma unroll
        for (int r = 0; r < 4; r++) o[dt][r] = 0.f;
    float mrow[2] = {-1e30f, -1e30f};
    float lrow[2] = {0.f, 0.f};

    const int kb_lo = max(0, q0 - (WIN - 1)) >> 5;
    const int kb_hi = (q0 + 63) >> 5;
    const int qw_lo = q0 + w * 16;
    const int gq_row = lane >> 2;
    const int t4 = lane & 3;

    issueK(kb_lo * 32);
    issueV(kb_lo * 32);

    for (int kb = kb_lo; kb <= kb_hi; kb++) {
        CP_WAIT0();
        __syncthreads();

        const int k0 = kb * 32;
        const bool active = (k0 <= qw_lo + 15) && (k0 + 31 >= qw_lo - (WIN - 1));
        const bool interior = (k0 + 31 <= qw_lo) && (k0 >= qw_lo + 16 - WIN);

        float s[4][4];
        uint32_t sl[4][2];

        if (active) {
#pragma unroll
            for (int tl = 0; tl < 4; tl++) {
#pragma unroll
                for (int r = 0; r < 4; r++) s[tl][r] = 0.f;
                sl[tl][0] = 0u; sl[tl][1] = 0u;
            }

#pragma unroll
            for (int dc = 0; dc < 16; dc++) {
                uint32_t qa[4], qb[4], k1h[4], k2h[4], k1l[4], k2l[4];
                int cb = dc * 2 + (lane >> 4);
                uint32_t qoff = swz(w * 16 + (lane & 15), cb);
                LDSM4(qa, sQh + qoff);
                LDSM4(qb, sQl + qoff);
                uint32_t koff = swz(lane & 15, cb);
                LDSM4(k1h, sKh + koff);
                LDSM4(k2h, sKh + koff + 16 * 512);
                LDSM4(k1l, sKl + koff);
                LDSM4(k2l, sKl + koff + 16 * 512);

                MMA_FP16(s[0], qa, k1h[0], k1h[2]);
                MMA_FP16(s[1], qa, k1h[1], k1h[3]);
                MMA_FP16(s[2], qa, k2h[0], k2h[2]);
                MMA_FP16(s[3], qa, k2h[1], k2h[3]);
                MMA_F16A(sl[0], qa, k1l[0], k1l[2]);
                MMA_F16A(sl[1], qa, k1l[1], k1l[3]);
                MMA_F16A(sl[2], qa, k2l[0], k2l[2]);
                MMA_F16A(sl[3], qa, k2l[1], k2l[3]);
                MMA_F16A(sl[0], qb, k1h[0], k1h[2]);
                MMA_F16A(sl[1], qb, k1h[1], k1h[3]);
                MMA_F16A(sl[2], qb, k2h[0], k2h[2]);
                MMA_F16A(sl[3], qb, k2h[1], k2h[3]);
            }
        }

        // all warps done reading sK — prefetch next K under softmax+PV
        __syncthreads();
        if (kb < kb_hi) issueK((kb + 1) * 32);

        if (active) {
#pragma unroll
            for (int tl = 0; tl < 4; tl++) {
                add_h2(&s[tl][0], sl[tl][0]);
                add_h2(&s[tl][2], sl[tl][1]);
            }

            float corr[2];
#pragma unroll
            for (int r = 0; r < 2; r++) {
                float mx = -1e30f;
                if (interior) {
#pragma unroll
                    for (int tl = 0; tl < 4; tl++)
                        mx = fmaxf(mx, fmaxf(s[tl][r * 2], s[tl][r * 2 + 1]));
                } else {
                    int qg = qw_lo + gq_row + r * 8;
#pragma unroll
                    for (int tl = 0; tl < 4; tl++) {
#pragma unroll
                        for (int c = 0; c < 2; c++) {
                            int kg = k0 + tl * 8 + 2 * t4 + c;
                            bool ok = (kg <= qg) && (qg - kg < WIN);
                            if (!ok) s[tl][r * 2 + c] = -1e30f;
                            mx = fmaxf(mx, s[tl][r * 2 + c]);
                        }
                    }
                }
                mx = fmaxf(mx, __shfl_xor_sync(0xffffffffu, mx, 1));
                mx = fmaxf(mx, __shfl_xor_sync(0xffffffffu, mx, 2));
                float m_new = fmaxf(mrow[r], mx);
                float mexp = (m_new <= -1e29f) ? 0.f : m_new;
                float sum = 0.f;
#pragma unroll
                for (int tl = 0; tl < 4; tl++) {
#pragma unroll
                    for (int c = 0; c < 2; c++) {
                        float p = __expf(s[tl][r * 2 + c] - mexp);
                        s[tl][r * 2 + c] = p;
                        sum += p;
                    }
                }
                sum += __shfl_xor_sync(0xffffffffu, sum, 1);
                sum += __shfl_xor_sync(0xffffffffu, sum, 2);
                corr[r] = __expf(mrow[r] - m_new);
                mrow[r] = m_new;
                lrow[r] = lrow[r] * corr[r] + sum;
            }

            // P -> single fp16 A-fragments
            uint32_t ph[2][4];
#pragma unroll
            for (int kc = 0; kc < 2; kc++) {
#pragma unroll
                for (int r2 = 0; r2 < 4; r2++) {
                    int tl = kc * 2 + (r2 >> 1);
                    int r  = r2 & 1;
                    __half2 hh = __halves2half2(__float2half_rn(s[tl][r * 2 + 0]),
                                                __float2half_rn(s[tl][r * 2 + 1]));
                    ph[kc][r2] = *(uint32_t*)&hh;
                }
            }

#pragma unroll
            for (int dt = 0; dt < 32; dt++) {
                o[dt][0] *= corr[0]; o[dt][1] *= corr[0];
                o[dt][2] *= corr[1]; o[dt][3] *= corr[1];
            }

#pragma unroll
            for (int dg = 0; dg < 16; dg++) {
#pragma unroll
                for (int kc = 0; kc < 2; kc++) {
                    uint32_t vh4[4];
                    int row_v = kc * 16 + (lane & 7) + ((lane >> 3) & 1) * 8;
                    int cb_v  = dg * 2 + ((lane >> 4) & 1);
                    LDSM4T(vh4, sVh + swz(row_v, cb_v));
                    MMA_FP16(o[2 * dg],     ph[kc], vh4[0], vh4[1]);
                    MMA_FP16(o[2 * dg + 1], ph[kc], vh4[2], vh4[3]);
                }
            }
        }

        // all warps done reading sV — prefetch next V
        __syncthreads();
        if (kb < kb_hi) issueV((kb + 1) * 32);
    }

    // finalize -> single fp16 output (wo GEMM is 1-pass)
    float inv0 = 1.f / lrow[0];
    float inv1 = 1.f / lrow[1];
    size_t r0 = (size_t)(q0 + w * 16 + gq_row) * QN + h * DH;
    size_t r1 = r0 + (size_t)8 * QN;
#pragma unroll
    for (int dt = 0; dt < 32; dt++) {
        int col = dt * 8 + 2 * t4;
        *(__half2*)(Oh + r0 + col) = __halves2half2(
            __float2half_rn(o[dt][0] * inv0), __float2half_rn(o[dt][1] * inv0));
        *(__half2*)(Oh + r1 + col) = __halves2half2(
            __float2half_rn(o[dt][2] * inv1), __float2half_rn(o[dt][3] * inv1));
    }
}

// =====================================================================
// kernel_launch
// =====================================================================
extern "C" void kernel_launch(void* const* d_in, const int* in_sizes, int n_in,
                              void* d_out, int out_size)
{
    const float* hs   = (const float*)d_in[0];
    const float* cosp = (const float*)d_in[1];
    const float* sinp = (const float*)d_in[2];
    const float* wq   = (const float*)d_in[3];
    const float* wk   = (const float*)d_in[4];
    const float* wv   = (const float*)d_in[5];
    const float* wo   = (const float*)d_in[6];
    const float* qw   = (const float*)d_in[7];
    const float* kw   = (const float*)d_in[8];
    float* out = (float*)d_out;

    float *gq, *gk, *gv;
    cudaGetSymbolAddress((void**)&gq, g_q);
    cudaGetSymbolAddress((void**)&gk, g_k);
    cudaGetSymbolAddress((void**)&gv, g_v);

    __half *hsh, *hsl, *wqh, *wql, *wkh, *wkl, *wvh, *woh, *ath;
    __half *qh, *ql, *kh, *kl, *vh;
    cudaGetSymbolAddress((void**)&hsh, g_hs_h); cudaGetSymbolAddress((void**)&hsl, g_hs_l);
    cudaGetSymbolAddress((void**)&wqh, g_wq_h); cudaGetSymbolAddress((void**)&wql, g_wq_l);
    cudaGetSymbolAddress((void**)&wkh, g_wk_h); cudaGetSymbolAddress((void**)&wkl, g_wk_l);
    cudaGetSymbolAddress((void**)&wvh, g_wv_h);
    cudaGetSymbolAddress((void**)&woh, g_wo_h);
    cudaGetSymbolAddress((void**)&ath, g_at_h);
    cudaGetSymbolAddress((void**)&qh, g_qh);    cudaGetSymbolAddress((void**)&ql, g_ql);
    cudaGetSymbolAddress((void**)&kh, g_kh);    cudaGetSymbolAddress((void**)&kl, g_kl);
    cudaGetSymbolAddress((void**)&vh, g_vh);

    cudaFuncSetAttribute(gemm_qkv_kernel, cudaFuncAttributeMaxDynamicSharedMemorySize,
                         GEMM64_SMEM);
    cudaFuncSetAttribute(gemm_wo_kernel, cudaFuncAttributeMaxDynamicSharedMemorySize,
                         GEMM64_SMEM);
    cudaFuncSetAttribute(attn_tc_kernel, cudaFuncAttributeMaxDynamicSharedMemorySize,
                         ATT_SM_BYTES);

    // all splits in one launch (wq,wk hi/lo; wv,wo hi-only)
    split_all_kernel<<<20480, 256>>>(hs, wq, wk, wv, wo,
                                     hsh, hsl, wqh, wql, wkh, wkl, wvh, woh);

    // fused QKV projections (q 3-pass; k 3-pass; v 1-pass), K-chunk 64
    gemm_qkv_kernel<<<dim3(32, S / 64), 256, GEMM64_SMEM>>>(
        hsh, hsl, wqh, wql, wkh, wkl, wvh, gq, gk, gv);

    // RMSNorm + RoPE
    norm_rope_kernel<<<S * 16 / 8, 256>>>(gq, gk, gv, cosp, sinp, qw, kw,
                                          qh, ql, kh, kl, vh);

    // attention (split K/V prefetch)
    attn_tc_kernel<<<dim3(S / 64, NH), 128, ATT_SM_BYTES>>>(
        qh, ql, kh, kl, vh, ath);

    // output projection — 1-pass, K-chunk 64
    gemm_wo_kernel<<<dim3(HID / 128, S / 64), 256, GEMM64_SMEM>>>(
        ath, woh, out);
}

// round 15
// speedup vs baseline: 1.0217x; 1.0217x over previous
#include <cuda_runtime.h>
#include <cuda_fp16.h>
#include <math.h>
#include <stdint.h>

// ---------------- problem constants ----------------
#define S     2048
#define HID   2560
#define NH    8
#define NKV   4
#define DH    256
#define WIN   1024
#define QN    (NH*DH)    // 2048
#define KVN   (NKV*DH)   // 1024

// ---------------- scratch ----------------
__device__ float g_q[S * QN];
__device__ float g_k[S * KVN];
__device__ float g_v[S * KVN];

__device__ __half g_hs_h[S * HID],  g_hs_l[S * HID];
__device__ __half g_wq_h[HID * QN], g_wq_l[HID * QN];
__device__ __half g_wk_h[HID * KVN], g_wk_l[HID * KVN];
__device__ __half g_wv_h[HID * KVN];
__device__ __half g_wo_h[QN * HID];
__device__ __half g_at_h[S * QN];

__device__ __half g_qh[S * QN],  g_ql[S * QN];
__device__ __half g_kh[S * KVN], g_kl[S * KVN];
__device__ __half g_vh[S * KVN];

// ---------------- PTX helpers ----------------
#define CP16(dst_u32, src_ptr) \
    asm volatile("cp.async.cg.shared.global [%0], [%1], 16;\n" :: "r"(dst_u32), "l"(src_ptr))
#define CP_COMMIT()  asm volatile("cp.async.commit_group;\n")
#define CP_WAIT0()   asm volatile("cp.async.wait_group 0;\n" ::: "memory")

#define LDSM4(R, addr) \
    asm volatile("ldmatrix.sync.aligned.m8n8.x4.shared.b16 {%0,%1,%2,%3}, [%4];\n" \
        : "=r"((R)[0]), "=r"((R)[1]), "=r"((R)[2]), "=r"((R)[3]) : "r"(addr))
#define LDSM4T(R, addr) \
    asm volatile("ldmatrix.sync.aligned.m8n8.x4.trans.shared.b16 {%0,%1,%2,%3}, [%4];\n" \
        : "=r"((R)[0]), "=r"((R)[1]), "=r"((R)[2]), "=r"((R)[3]) : "r"(addr))

#define MMA_FP16(d, a, b0, b1) \
    asm volatile("mma.sync.aligned.m16n8k16.row.col.f32.f16.f16.f32 " \
        "{%0,%1,%2,%3},{%4,%5,%6,%7},{%8,%9},{%0,%1,%2,%3};\n" \
        : "+f"((d)[0]), "+f"((d)[1]), "+f"((d)[2]), "+f"((d)[3]) \
        : "r"((a)[0]), "r"((a)[1]), "r"((a)[2]), "r"((a)[3]), "r"(b0), "r"(b1))

#define MMA_F16A(d, a, b0, b1) \
    asm volatile("mma.sync.aligned.m16n8k16.row.col.f16.f16.f16.f16 " \
        "{%0,%1},{%2,%3,%4,%5},{%6,%7},{%0,%1};\n" \
        : "+r"((d)[0]), "+r"((d)[1]) \
        : "r"((a)[0]), "r"((a)[1]), "r"((a)[2]), "r"((a)[3]), "r"(b0), "r"(b1))

__device__ __forceinline__ uint32_t smem_u32(const void* p) {
    return (uint32_t)__cvta_generic_to_shared(p);
}
__device__ __forceinline__ void add_h2(float* f01, uint32_t packed) {
    __half2 h = *(__half2*)&packed;
    float2 v = __half22float2(h);
    f01[0] += v.x; f01[1] += v.y;
}
// XOR swizzle for 512B rows
__device__ __forceinline__ uint32_t swz(int row, int cb) {
    return (uint32_t)(row * 512 + ((cb ^ (row & 7)) << 4));
}

// =====================================================================
// Static balanced work map for attention.
// Unit (x, h): q-tile x (cost = min(2x+2, 34) keyblocks), head h.
// SM s co-hosts CTAs s and s+148 → pair heavy(34)+small-light(<=22),
// pair large lights together (<=56), 40 heavies single.
// =====================================================================
__device__ __forceinline__ void decode_unit(int c, int& x, int& h) {
    if (c < 88) {                       // heavy members of heavy+light pairs
        x = 16 + (c & 15); h = c >> 4;
    } else if (c < 108) {               // large-light pair: first member
        int j = c - 88;
        if (j < 8)       { x = 11; h = j; }
        else if (j < 16) { x = 12; h = j - 8; }
        else             { x = 13; h = j - 16; }
    } else if (c < 148) {               // singles: remaining heavies
        int j = 88 + (c - 108);
        x = 16 + (j & 15); h = j >> 4;
    } else if (c < 236) {               // small lights (partners of c-148)
        int j = c - 148;
        x = j >> 3; h = j & 7;
    } else {                            // large-light pair: second member
        int j = c - 236;
        if (j < 8)       { x = 15; h = j; }
        else if (j < 16) { x = 14; h = j - 8; }
        else             { x = 13; h = j - 16 + 4; }
    }
}

// =====================================================================
// Fused split kernel (one launch). wq,wk: hi/lo. wv,wo: hi only.
// =====================================================================
__global__ __launch_bounds__(256) void split_all_kernel(
    const float* __restrict__ hs, const float* __restrict__ wq,
    const float* __restrict__ wk, const float* __restrict__ wv,
    const float* __restrict__ wo,
    __half* __restrict__ hsh, __half* __restrict__ hsl,
    __half* __restrict__ wqh, __half* __restrict__ wql,
    __half* __restrict__ wkh, __half* __restrict__ wkl,
    __half* __restrict__ wvh, __half* __restrict__ woh)
{
    int b = blockIdx.x;
    const float* x; __half *h, *l;
    if (b < 5120)       { x = hs; h = hsh; l = hsl; }
    else if (b < 10240) { x = wq; h = wqh; l = wql; b -= 5120; }
    else if (b < 12800) { x = wk; h = wkh; l = wkl; b -= 10240; }
    else if (b < 15360) { x = wv; h = wvh; l = nullptr; b -= 12800; }
    else                { x = wo; h = woh; l = nullptr; b -= 15360; }

    int i = (b * 256 + threadIdx.x) * 4;
    float4 v = *(const float4*)(x + i);
    __half h0 = __float2half_rn(v.x), h1 = __float2half_rn(v.y);
    __half h2 = __float2half_rn(v.z), h3 = __float2half_rn(v.w);
    *(__half2*)(h + i)     = __halves2half2(h0, h1);
    *(__half2*)(h + i + 2) = __halves2half2(h2, h3);
    if (l) {
        *(__half2*)(l + i)     = __halves2half2(
            __float2half_rn(v.x - __half2float(h0)), __float2half_rn(v.y - __half2float(h1)));
        *(__half2*)(l + i + 2) = __halves2half2(
            __float2half_rn(v.z - __half2float(h2)), __float2half_rn(v.w - __half2float(h3)));
    }
}

// =====================================================================
// fp16 TC GEMM body — PASSES compile-time. 64-row M tiles, K-chunk 64.
// =====================================================================
#define A64_STR 72
#define B64_STR 136
#define A64_E   (64 * A64_STR)
#define B64_E   (64 * B64_STR)
#define G64_BUF (2 * A64_E + 2 * B64_E)
#define GEMM64_SMEM (2 * G64_BUF * 2)

template <int PASSES>
__device__ __forceinline__ void gemm_body(
    const __half* __restrict__ Ah, const __half* __restrict__ Al,
    const __half* __restrict__ Bh, const __half* __restrict__ Bl,
    float* __restrict__ C, int N, int K, int m0, int n0,
    __half* smbuf)
{
    const int t    = threadIdx.x;
    const int lane = t & 31;
    const int wid  = t >> 5;
    const int wm   = wid >> 2;
    const int wn   = wid & 3;

    float acc[2][4][4];
    uint32_t accL[2][4][2];
#pragma unroll
    for (int mi = 0; mi < 2; mi++)
#pragma unroll
        for (int ni = 0; ni < 4; ni++) {
#pragma unroll
            for (int r = 0; r < 4; r++) acc[mi][ni][r] = 0.f;
            accL[mi][ni][0] = 0u; accL[mi][ni][1] = 0u;
        }

    uint32_t sbase[2][4];
#pragma unroll
    for (int b = 0; b < 2; b++) {
        __half* p = smbuf + b * G64_BUF;
        sbase[b][0] = smem_u32(p);
        sbase[b][1] = smem_u32(p + A64_E);
        sbase[b][2] = smem_u32(p + 2 * A64_E);
        sbase[b][3] = smem_u32(p + 2 * A64_E + B64_E);
    }

    auto issue = [&](int k0, int buf) {
#pragma unroll
        for (int p = 0; p < 2; p++) {
            int id = t + p * 256;
            int row = id >> 3, c8 = (id & 7) * 8;
            size_t aoff = (size_t)(m0 + row) * K + k0 + c8;
            uint32_t ad = (uint32_t)(row * A64_STR + c8) * 2;
            CP16(sbase[buf][0] + ad, Ah + aoff);
            if (PASSES >= 2) CP16(sbase[buf][1] + ad, Al + aoff);
        }
#pragma unroll
        for (int p = 0; p < 4; p++) {
            int id = t + p * 256;
            int row = id >> 4, c8 = (id & 15) * 8;
            size_t boff = (size_t)(k0 + row) * N + n0 + c8;
            uint32_t bd = (uint32_t)(row * B64_STR + c8) * 2;
            CP16(sbase[buf][2] + bd, Bh + boff);
            if (PASSES == 3) CP16(sbase[buf][3] + bd, Bl + boff);
        }
        CP_COMMIT();
    };

    issue(0, 0);
    const int nIter = K / 64;

    for (int it = 0; it < nIter; it++) {
        CP_WAIT0();
        __syncthreads();
        if (it + 1 < nIter) issue((it + 1) * 64, (it + 1) & 1);

        const int buf = it & 1;
        const uint32_t ah_s = sbase[buf][0];
        const uint32_t al_s = sbase[buf][1];
        const uint32_t bh_s = sbase[buf][2];
        const uint32_t bl_s = sbase[buf][3];

#pragma unroll
        for (int ks = 0; ks < 64; ks += 16) {
            uint32_t fah[2][4], fal[2][4], fbh[2][4], fbl[2][4];

            int arow = lane & 15;
            int acol = ks + ((lane >> 4) & 1) * 8;
#pragma unroll
            for (int mi = 0; mi < 2; mi++) {
                uint32_t off = (uint32_t)((wm * 32 + mi * 16 + arow) * A64_STR + acol) * 2;
                LDSM4(fah[mi], ah_s + off);
                if (PASSES >= 2) LDSM4(fal[mi], al_s + off);
            }

            int bkrow = ks + (lane & 7) + ((lane >> 3) & 1) * 8;
#pragma unroll
            for (int np = 0; np < 2; np++) {
                int bcol = wn * 32 + np * 16 + ((lane >> 4) & 1) * 8;
                uint32_t off = (uint32_t)(bkrow * B64_STR + bcol) * 2;
                LDSM4T(fbh[np], bh_s + off);
                if (PASSES == 3) LDSM4T(fbl[np], bl_s + off);
            }

#pragma unroll
            for (int mi = 0; mi < 2; mi++)
#pragma unroll
                for (int ni = 0; ni < 4; ni++) {
                    const uint32_t* bh2 = &fbh[ni >> 1][(ni & 1) * 2];
                    MMA_FP16(acc[mi][ni], fah[mi], bh2[0], bh2[1]);
                    if (PASSES >= 2) MMA_F16A(accL[mi][ni], fal[mi], bh2[0], bh2[1]);
                    if (PASSES == 3) {
                        const uint32_t* bl2 = &fbl[ni >> 1][(ni & 1) * 2];
                        MMA_F16A(accL[mi][ni], fah[mi], bl2[0], bl2[1]);
                    }
                }
        }
        __syncthreads();
    }

    int g  = lane >> 2;
    int c2 = (lane & 3) * 2;
#pragma unroll
    for (int mi = 0; mi < 2; mi++)
#pragma unroll
        for (int ni = 0; ni < 4; ni++) {
            if (PASSES >= 2) {
                add_h2(&acc[mi][ni][0], accL[mi][ni][0]);
                add_h2(&acc[mi][ni][2], accL[mi][ni][1]);
            }
            int row = m0 + wm * 32 + mi * 16 + g;
            int col = n0 + wn * 32 + ni * 8 + c2;
            *(float2*)(C + (size_t)row * N + col)       = make_float2(acc[mi][ni][0], acc[mi][ni][1]);
            *(float2*)(C + (size_t)(row + 8) * N + col) = make_float2(acc[mi][ni][2], acc[mi][ni][3]);
        }
}

// fused QKV projection — q 3-pass; k 3-pass; v 1-pass
__global__ __launch_bounds__(256) void gemm_qkv_kernel(
    const __half* __restrict__ Ah, const __half* __restrict__ Al,
    const __half* __restrict__ wqh, const __half* __restrict__ wql,
    const __half* __restrict__ wkh, const __half* __restrict__ wkl,
    const __half* __restrict__ wvh,
    float* __restrict__ gq, float* __restrict__ gk, float* __restrict__ gv)
{
    extern __shared__ __half smbuf[];
    const int bx = blockIdx.x;
    const int m0 = blockIdx.y * 64;
    if (bx < 16)
        gemm_body<3>(Ah, Al, wqh, wql, gq, QN, HID, m0, bx * 128, smbuf);
    else if (bx < 24)
        gemm_body<3>(Ah, Al, wkh, wkl, gk, KVN, HID, m0, (bx - 16) * 128, smbuf);
    else
        gemm_body<1>(Ah, Ah, wvh, wvh, gv, KVN, HID, m0, (bx - 24) * 128, smbuf);
}

// output projection — 1-pass
__global__ __launch_bounds__(256) void gemm_wo_kernel(
    const __half* __restrict__ Ah,
    const __half* __restrict__ Bh, float* __restrict__ C)
{
    extern __shared__ __half smbuf[];
    gemm_body<1>(Ah, Ah, Bh, Bh, C, HID, QN, blockIdx.y * 64, blockIdx.x * 128, smbuf);
}

// =====================================================================
// Fused RMSNorm (+weight) + RoPE — warp-per-head (unchanged)
// =====================================================================
__global__ __launch_bounds__(256) void norm_rope_kernel(
    const float* __restrict__ q, const float* __restrict__ k, const float* __restrict__ v,
    const float* __restrict__ cosp, const float* __restrict__ sinp,
    const float* __restrict__ qw, const float* __restrict__ kw,
    __half* __restrict__ qh, __half* __restrict__ ql,
    __half* __restrict__ kh, __half* __restrict__ kl,
    __half* __restrict__ vh)
{
    const int lane = threadIdx.x & 31;
    const int row  = blockIdx.x * 8 + (threadIdx.x >> 5);
    const int s    = row >> 4;
    const int idx  = row & 15;

    const float* base;
    const float* w;
    __half *oh, *ol;
    bool rope;
    if (idx < 8) {
        base = q + (size_t)s * QN + idx * DH; w = qw; rope = true;
        oh = qh + (size_t)s * QN + idx * DH; ol = ql + (size_t)s * QN + idx * DH;
    } else if (idx < 12) {
        base = k + (size_t)s * KVN + (idx - 8) * DH; w = kw; rope = true;
        oh = kh + (size_t)s * KVN + (idx - 8) * DH; ol = kl + (size_t)s * KVN + (idx - 8) * DH;
    } else {
        base = v + (size_t)s * KVN + (idx - 12) * DH; w = nullptr; rope = false;
        oh = vh + (size_t)s * KVN + (idx - 12) * DH; ol = nullptr;
    }

    const int d0 = lane * 8;
    float x[8];
    *(float4*)&x[0] = *(const float4*)(base + d0);
    *(float4*)&x[4] = *(const float4*)(base + d0 + 4);

    float ss = 0.f;
#pragma unroll
    for (int j = 0; j < 8; j++) ss += x[j] * x[j];
#pragma unroll
    for (int o = 16; o; o >>= 1) ss += __shfl_xor_sync(0xffffffffu, ss, o);

    float inv = rsqrtf(ss * (1.0f / 256.0f) + 1e-6f);
    float y[8];
#pragma unroll
    for (int j = 0; j < 8; j++) y[j] = x[j] * inv;
    if (w) {
        float wv[8];
        *(float4*)&wv[0] = *(const float4*)(w + d0);
        *(float4*)&wv[4] = *(const float4*)(w + d0 + 4);
#pragma unroll
        for (int j = 0; j < 8; j++) y[j] *= wv[j];
    }

    float out[8];
    if (rope) {
        float c[8], si[8];
        *(float4*)&c[0]  = *(const float4*)(cosp + (size_t)s * DH + d0);
        *(float4*)&c[4]  = *(const float4*)(cosp + (size_t)s * DH + d0 + 4);
        *(float4*)&si[0] = *(const float4*)(sinp + (size_t)s * DH + d0);
        *(float4*)&si[4] = *(const float4*)(sinp + (size_t)s * DH + d0 + 4);
#pragma unroll
        for (int j = 0; j < 8; j++) {
            float pv = __shfl_xor_sync(0xffffffffu, y[j], 16);
            float rh = (lane < 16) ? -pv : pv;
            out[j] = y[j] * c[j] + rh * si[j];
        }
    } else {
#pragma unroll
        for (int j = 0; j < 8; j++) out[j] = y[j];
    }

    __half hi8[8], lo8[8];
#pragma unroll
    for (int j = 0; j < 8; j++) {
        hi8[j] = __float2half_rn(out[j]);
        lo8[j] = __float2half_rn(out[j] - __half2float(hi8[j]));
    }
    *(uint4*)(oh + d0) = *(uint4*)hi8;
    if (ol) *(uint4*)(ol + d0) = *(uint4*)lo8;
}

// =====================================================================
// TC flash attention: 64-q tiles, 4 warps, 2 CTAs/SM.
// QK 3-pass; PV single-pass; interior fast-path.
// R12 loop structure (single KV commit group) + balanced work map.
// =====================================================================
#define ATT_SM_BYTES (2 * 64 * 512 + 3 * 32 * 512)   // 114688

__global__ __launch_bounds__(128, 2) void attn_tc_kernel(
    const __half* __restrict__ Qh, const __half* __restrict__ Ql,
    const __half* __restrict__ Kh, const __half* __restrict__ Kl,
    const __half* __restrict__ Vh,
    __half* __restrict__ Oh)
{
    extern __shared__ __half sm2[];
    const int t    = threadIdx.x;
    const int lane = t & 31;
    const int w    = t >> 5;

    int xt, h;
    decode_unit(blockIdx.x, xt, h);
    const int q0  = xt * 64;
    const int kvh = h >> 1;

    const uint32_t sQh = smem_u32(sm2);
    const uint32_t sQl = sQh + 64 * 512;
    const uint32_t sKh = sQl + 64 * 512;
    const uint32_t sKl = sKh + 32 * 512;
    const uint32_t sVh = sKl + 32 * 512;

    // ---- Q load ----
    const __half* gqh = Qh + (size_t)q0 * QN + h * DH;
    const __half* gql = Ql + (size_t)q0 * QN + h * DH;
#pragma unroll
    for (int it = 0; it < 16; it++) {
        int id = t + it * 128;
        int row = id >> 5, cb = id & 31;
        uint32_t d = swz(row, cb);
        size_t g = (size_t)row * QN + cb * 8;
        CP16(sQh + d, gqh + g);
        CP16(sQl + d, gql + g);
    }
    CP_COMMIT();

    auto issueKV = [&](int k0) {
        const __half* gkh = Kh + (size_t)k0 * KVN + kvh * DH;
        const __half* gkl = Kl + (size_t)k0 * KVN + kvh * DH;
        const __half* gvh = Vh + (size_t)k0 * KVN + kvh * DH;
#pragma unroll
        for (int it = 0; it < 8; it++) {
            int id = t + it * 128;
            int row = id >> 5, cb = id & 31;
            uint32_t d = swz(row, cb);
            size_t g = (size_t)row * KVN + cb * 8;
            CP16(sKh + d, gkh + g);
            CP16(sKl + d, gkl + g);
            CP16(sVh + d, gvh + g);
        }
        CP_COMMIT();
    };

    float o[32][4];
#pragma unroll
    for (int dt = 0; dt < 32; dt++)
#pragma unroll
        for (int r = 0; r < 4; r++) o[dt][r] = 0.f;
    float mrow[2] = {-1e30f, -1e30f};
    float lrow[2] = {0.f, 0.f};

    const int kb_lo = max(0, q0 - (WIN - 1)) >> 5;
    const int kb_hi = (q0 + 63) >> 5;
    const int qw_lo = q0 + w * 16;
    const int gq_row = lane >> 2;
    const int t4 = lane & 3;

    issueKV(kb_lo * 32);

    for (int kb = kb_lo; kb <= kb_hi; kb++) {
        CP_WAIT0();
        __syncthreads();

        const int k0 = kb * 32;
        const bool active = (k0 <= qw_lo + 15) && (k0 + 31 >= qw_lo - (WIN - 1));
        if (active) {
            const bool interior = (k0 + 31 <= qw_lo) && (k0 >= qw_lo + 16 - WIN);

            float s[4][4];
            uint32_t sl[4][2];
#pragma unroll
            for (int tl = 0; tl < 4; tl++) {
#pragma unroll
                for (int r = 0; r < 4; r++) s[tl][r] = 0.f;
                sl[tl][0] = 0u; sl[tl][1] = 0u;
            }

#pragma unroll
            for (int dc = 0; dc < 16; dc++) {
                uint32_t qa[4], qb[4], k1h[4], k2h[4], k1l[4], k2l[4];
                int cb = dc * 2 + (lane >> 4);
                uint32_t qoff = swz(w * 16 + (lane & 15), cb);
                LDSM4(qa, sQh + qoff);
                LDSM4(qb, sQl + qoff);
                uint32_t koff = swz(lane & 15, cb);
                LDSM4(k1h, sKh + koff);
                LDSM4(k2h, sKh + koff + 16 * 512);
                LDSM4(k1l, sKl + koff);
                LDSM4(k2l, sKl + koff + 16 * 512);

                MMA_FP16(s[0], qa, k1h[0], k1h[2]);
                MMA_FP16(s[1], qa, k1h[1], k1h[3]);
                MMA_FP16(s[2], qa, k2h[0], k2h[2]);
                MMA_FP16(s[3], qa, k2h[1], k2h[3]);
                MMA_F16A(sl[0], qa, k1l[0], k1l[2]);
                MMA_F16A(sl[1], qa, k1l[1], k1l[3]);
                MMA_F16A(sl[2], qa, k2l[0], k2l[2]);
                MMA_F16A(sl[3], qa, k2l[1], k2l[3]);
                MMA_F16A(sl[0], qb, k1h[0], k1h[2]);
                MMA_F16A(sl[1], qb, k1h[1], k1h[3]);
                MMA_F16A(sl[2], qb, k2h[0], k2h[2]);
                MMA_F16A(sl[3], qb, k2h[1], k2h[3]);
            }
#pragma unroll
            for (int tl = 0; tl < 4; tl++) {
                add_h2(&s[tl][0], sl[tl][0]);
                add_h2(&s[tl][2], sl[tl][1]);
            }

            float corr[2];
#pragma unroll
            for (int r = 0; r < 2; r++) {
                float mx = -1e30f;
                if (interior) {
#pragma unroll
                    for (int tl = 0; tl < 4; tl++)
                        mx = fmaxf(mx, fmaxf(s[tl][r * 2], s[tl][r * 2 + 1]));
                } else {
                    int qg = qw_lo + gq_row + r * 8;
#pragma unroll
                    for (int tl = 0; tl < 4; tl++) {
#pragma unroll
                        for (int c = 0; c < 2; c++) {
                            int kg = k0 + tl * 8 + 2 * t4 + c;
                            bool ok = (kg <= qg) && (qg - kg < WIN);
                            if (!ok) s[tl][r * 2 + c] = -1e30f;
                            mx = fmaxf(mx, s[tl][r * 2 + c]);
                        }
                    }
                }
                mx = fmaxf(mx, __shfl_xor_sync(0xffffffffu, mx, 1));
                mx = fmaxf(mx, __shfl_xor_sync(0xffffffffu, mx, 2));
                float m_new = fmaxf(mrow[r], mx);
                float mexp = (m_new <= -1e29f) ? 0.f : m_new;
                float sum = 0.f;
#pragma unroll
                for (int tl = 0; tl < 4; tl++) {
#pragma unroll
                    for (int c = 0; c < 2; c++) {
                        float p = __expf(s[tl][r * 2 + c] - mexp);
                        s[tl][r * 2 + c] = p;
                        sum += p;
                    }
                }
                sum += __shfl_xor_sync(0xffffffffu, sum, 1);
                sum += __shfl_xor_sync(0xffffffffu, sum, 2);
                corr[r] = __expf(mrow[r] - m_new);
                mrow[r] = m_new;
                lrow[r] = lrow[r] * corr[r] + sum;
            }

            // P -> single fp16 A-fragments
            uint32_t ph[2][4];
#pragma unroll
            for (int kc = 0; kc < 2; kc++) {
#pragma unroll
                for (int r2 = 0; r2 < 4; r2++) {
                    int tl = kc * 2 + (r2 >> 1);
                    int r  = r2 & 1;
                    __half2 hh = __halves2half2(__float2half_rn(s[tl][r * 2 + 0]),
                                                __float2half_rn(s[tl][r * 2 + 1]));
                    ph[kc][r2] = *(uint32_t*)&hh;
                }
            }

#pragma unroll
            for (int dt = 0; dt < 32; dt++) {
                o[dt][0] *= corr[0]; o[dt][1] *= corr[0];
                o[dt][2] *= corr[1]; o[dt][3] *= corr[1];
            }

#pragma unroll
            for (int dg = 0; dg < 16; dg++) {
#pragma unroll
                for (int kc = 0; kc < 2; kc++) {
                    uint32_t vh4[4];
                    int row_v = kc * 16 + (lane & 7) + ((lane >> 3) & 1) * 8;
                    int cb_v  = dg * 2 + ((lane >> 4) & 1);
                    LDSM4T(vh4, sVh + swz(row_v, cb_v));
                    MMA_FP16(o[2 * dg],     ph[kc], vh4[0], vh4[1]);
                    MMA_FP16(o[2 * dg + 1], ph[kc], vh4[2], vh4[3]);
                }
            }
        }
        __syncthreads();
        if (kb < kb_hi) issueKV((kb + 1) * 32);
    }

    // finalize -> single fp16 output (wo GEMM is 1-pass)
    float inv0 = 1.f / lrow[0];
    float inv1 = 1.f / lrow[1];
    size_t r0 = (size_t)(q0 + w * 16 + gq_row) * QN + h * DH;
    size_t r1 = r0 + (size_t)8 * QN;
#pragma unroll
    for (int dt = 0; dt < 32; dt++) {
        int col = dt * 8 + 2 * t4;
        *(__half2*)(Oh + r0 + col) = __halves2half2(
            __float2half_rn(o[dt][0] * inv0), __float2half_rn(o[dt][1] * inv0));
        *(__half2*)(Oh + r1 + col) = __halves2half2(
            __float2half_rn(o[dt][2] * inv1), __float2half_rn(o[dt][3] * inv1));
    }
}

// =====================================================================
// kernel_launch
// =====================================================================
extern "C" void kernel_launch(void* const* d_in, const int* in_sizes, int n_in,
                              void* d_out, int out_size)
{
    const float* hs   = (const float*)d_in[0];
    const float* cosp = (const float*)d_in[1];
    const float* sinp = (const float*)d_in[2];
    const float* wq   = (const float*)d_in[3];
    const float* wk   = (const float*)d_in[4];
    const float* wv   = (const float*)d_in[5];
    const float* wo   = (const float*)d_in[6];
    const float* qw   = (const float*)d_in[7];
    const float* kw   = (const float*)d_in[8];
    float* out = (float*)d_out;

    float *gq, *gk, *gv;
    cudaGetSymbolAddress((void**)&gq, g_q);
    cudaGetSymbolAddress((void**)&gk, g_k);
    cudaGetSymbolAddress((void**)&gv, g_v);

    __half *hsh, *hsl, *wqh, *wql, *wkh, *wkl, *wvh, *woh, *ath;
    __half *qh, *ql, *kh, *kl, *vh;
    cudaGetSymbolAddress((void**)&hsh, g_hs_h); cudaGetSymbolAddress((void**)&hsl, g_hs_l);
    cudaGetSymbolAddress((void**)&wqh, g_wq_h); cudaGetSymbolAddress((void**)&wql, g_wq_l);
    cudaGetSymbolAddress((void**)&wkh, g_wk_h); cudaGetSymbolAddress((void**)&wkl, g_wk_l);
    cudaGetSymbolAddress((void**)&wvh, g_wv_h);
    cudaGetSymbolAddress((void**)&woh, g_wo_h);
    cudaGetSymbolAddress((void**)&ath, g_at_h);
    cudaGetSymbolAddress((void**)&qh, g_qh);    cudaGetSymbolAddress((void**)&ql, g_ql);
    cudaGetSymbolAddress((void**)&kh, g_kh);    cudaGetSymbolAddress((void**)&kl, g_kl);
    cudaGetSymbolAddress((void**)&vh, g_vh);

    cudaFuncSetAttribute(gemm_qkv_kernel, cudaFuncAttributeMaxDynamicSharedMemorySize,
                         GEMM64_SMEM);
    cudaFuncSetAttribute(gemm_wo_kernel, cudaFuncAttributeMaxDynamicSharedMemorySize,
                         GEMM64_SMEM);
    cudaFuncSetAttribute(attn_tc_kernel, cudaFuncAttributeMaxDynamicSharedMemorySize,
                         ATT_SM_BYTES);

    // all splits in one launch (wq,wk hi/lo; wv,wo hi-only)
    split_all_kernel<<<20480, 256>>>(hs, wq, wk, wv, wo,
                                     hsh, hsl, wqh, wql, wkh, wkl, wvh, woh);

    // fused QKV projections (q 3-pass; k 3-pass; v 1-pass), K-chunk 64
    gemm_qkv_kernel<<<dim3(32, S / 64), 256, GEMM64_SMEM>>>(
        hsh, hsl, wqh, wql, wkh, wkl, wvh, gq, gk, gv);

    // RMSNorm + RoPE
    norm_rope_kernel<<<S * 16 / 8, 256>>>(gq, gk, gv, cosp, sinp, qw, kw,
                                          qh, ql, kh, kl, vh);

    // attention — balanced static schedule, 256 CTAs
    attn_tc_kernel<<<256, 128, ATT_SM_BYTES>>>(
        qh, ql, kh, kl, vh, ath);

    // output projection — 1-pass, K-chunk 64
    gemm_wo_kernel<<<dim3(HID / 128, S / 64), 256, GEMM64_SMEM>>>(
        ath, woh, out);
}